// round 9
// baseline (speedup 1.0000x reference)
#include <cuda_runtime.h>
#include <cuda_bf16.h>
#include <cstdint>

// ---------------- problem constants -----------------------------------------
static constexpr int BB = 16, CIN = 64, H = 32, W = 32, COUT = 64;
static constexpr int GS = 8;                  // grid_size + spline_order
static constexpr int HP = 34, WP = 34;        // padded spatial
static constexpr int CK = CIN * GS;           // 512 effective channels

// ---------------- device scratch (no allocations allowed) -------------------
// basis planes, channel-last, tf32-rounded fp32, k-permuted within each 8-block:
// [b][hp][wp][c']  where slot(g) = ((g<<1)&7)|(g>>2)  (pairs (t,t+4) adjacent)
__device__ __align__(16) float g_yf[BB * HP * WP * CK];   // ~37.9 MB
// folded weights, tf32-rounded fp32, same k permutation: [tap][o][c']
__device__ __align__(16) float g_wt[9 * COUT * CK];

// ---------------- helpers -----------------------------------------------------
__device__ __forceinline__ uint32_t smem_u32(const void* p) {
    uint32_t a;
    asm("{ .reg .u64 t; cvta.to.shared.u64 t, %1; cvt.u32.u64 %0, t; }"
        : "=r"(a) : "l"(p));
    return a;
}
__device__ __forceinline__ void cp16(uint32_t dst, const void* src) {
    asm volatile("cp.async.ca.shared.global [%0], [%1], 16;"
                 :: "r"(dst), "l"(src) : "memory");
}
__device__ __forceinline__ void lds64(uint32_t addr, uint32_t& r0, uint32_t& r1) {
    asm volatile("ld.shared.v2.b32 {%0,%1}, [%2];"
                 : "=r"(r0), "=r"(r1) : "r"(addr));
}
__device__ __forceinline__ void mma1688(float* c, uint32_t a0, uint32_t a1,
                                        uint32_t a2, uint32_t a3,
                                        uint32_t b0, uint32_t b1) {
    asm volatile(
        "mma.sync.aligned.m16n8k8.row.col.f32.tf32.tf32.f32 "
        "{%0,%1,%2,%3}, {%4,%5,%6,%7}, {%8,%9}, {%0,%1,%2,%3};"
        : "+f"(c[0]), "+f"(c[1]), "+f"(c[2]), "+f"(c[3])
        : "r"(a0), "r"(a1), "r"(a2), "r"(a3), "r"(b0), "r"(b1));
}
__device__ __forceinline__ float tf32r(float v) {
    uint32_t u;
    asm("cvt.rna.tf32.f32 %0, %1;" : "=r"(u) : "f"(v));
    return __uint_as_float(u);
}

// ---------------- kernel 1: weight fold + tf32 round + k-permute ------------
__global__ void wprep_kernel(const float* __restrict__ sw,
                             const float* __restrict__ sc) {
    int t = blockIdx.x * blockDim.x + threadIdx.x;
    if (t >= 9 * COUT * CK) return;
    int c = t & 511;
    int o = (t >> 9) & 63;
    int tap = t >> 15;
    int i = c >> 3, g = c & 7;
    float v = sw[((o * CIN + i) * GS + g) * 9 + tap] * sc[o * CIN + i];
    int slot = ((g << 1) & 7) | (g >> 2);        // k-permute within 8-block
    g_wt[(t & ~7) | slot] = tf32r(v);
}

// ---------------- kernel 2: B-spline basis, tf32 fp32, k-permuted ------------
__global__ void basis_kernel(const float* __restrict__ x) {
    int idx = blockIdx.x * blockDim.x + threadIdx.x;
    if (idx >= BB * HP * WP * CIN) return;
    int i = idx & 63;
    int t = idx >> 6;
    int wp = t % WP; t /= WP;
    int hp = t % HP;
    int b = t / HP;

    float xv = 0.0f;
    int h = hp - 1, w = wp - 1;
    if ((unsigned)h < (unsigned)H && (unsigned)w < (unsigned)W)
        xv = x[((b * CIN + i) * H + h) * W + w];

    float gk[12];
#pragma unroll
    for (int j = 0; j < 12; j++) gk[j] = (float)(j - 3) * 0.4f - 1.0f;
    float b0[11];
#pragma unroll
    for (int j = 0; j < 11; j++)
        b0[j] = (xv >= gk[j] && xv < gk[j + 1]) ? 1.0f : 0.0f;
    float b1[10];
#pragma unroll
    for (int j = 0; j < 10; j++)
        b1[j] = ((xv - gk[j]) * b0[j] + (gk[j + 2] - xv) * b0[j + 1]) * 2.5f;
    float b2[9];
#pragma unroll
    for (int j = 0; j < 9; j++)
        b2[j] = ((xv - gk[j]) * b1[j] + (gk[j + 3] - xv) * b1[j + 1]) * 1.25f;
    float b3[8];
#pragma unroll
    for (int j = 0; j < 8; j++)
        b3[j] = ((xv - gk[j]) * b2[j] + (gk[j + 4] - xv) * b2[j + 1]) * (1.0f / 1.2f);

    float f[8];
#pragma unroll
    for (int g = 0; g < GS; g++) {
        int slot = ((g << 1) & 7) | (g >> 2);
        f[slot] = tf32r(b3[g]);
    }
    float4* dst = (float4*)(g_yf + (size_t)idx * 8);
    dst[0] = make_float4(f[0], f[1], f[2], f[3]);
    dst[1] = make_float4(f[4], f[5], f[6], f[7]);
}

// ---------------- kernel 3: tf32 mma.sync conv, m32n64 warps -----------------
// CTA: M=64 pixels (batch b, 2 rows x 32 cols), N=64 outs, 64 thr / 2 warps.
// Warp wm in {0,1}: m-tile 32 (one output row) x n-tile 64 (all outs).
// Chunk-major K loop: A block (4 rows x 34 cols x 64 ch, 34.8 KB) staged once
// per chunk; 9 taps run from it via shifted addressing. B double-buffered.
static constexpr int A_BYTES = 136 * 256;        // 34816
static constexpr int B_BYTES = 16384;
static constexpr int SMEM_TOTAL = A_BYTES + 2 * B_BYTES + 256;

__global__ __launch_bounds__(64, 3) void conv_kernel(float* __restrict__ out) {
    extern __shared__ char smem[];
    uint32_t sraw = smem_u32(smem);
    uint32_t sb = (sraw + 255u) & ~255u;
    uint32_t Ab = sb;
    uint32_t Bb0 = sb + A_BYTES;

    int tid = threadIdx.x;
    int blk = blockIdx.x;
    int bb = blk >> 4;            // batch
    int h0 = (blk & 15) * 2;      // output row base

    int lane = tid & 31;
    int wm = tid >> 5;            // 0..1
    int g = lane >> 2, t4 = lane & 3;

    // B smem offsets (XOR ks<<5 at use): row o = nf*8 + g, key = g
    uint32_t boff[8];
#pragma unroll
    for (int nf = 0; nf < 8; nf++)
        boff[nf] = (uint32_t)((nf * 8 + g) * 256 + t4 * 8 + (g << 5));

    float acc[2][8][4];           // [mt][nf][i]
#pragma unroll
    for (int a = 0; a < 2; a++)
#pragma unroll
        for (int b = 0; b < 8; b++)
#pragma unroll
            for (int i = 0; i < 4; i++) acc[a][b][i] = 0.0f;

    const uint4* yf4 = (const uint4*)g_yf;
    const uint4* wt4 = (const uint4*)g_wt;

    // ---- A block stage: 4 rows x 34 cols x 64 ch of chunk `ch` --------------
    auto issueA = [&](int ch) {
        int cw0 = ch * 16;
#pragma unroll
        for (int k = 0; k < 34; k++) {
            int q = tid + k * 64;              // 0..2175
            int pix = q >> 4, c4 = q & 15;
            int r = pix / 34, wp = pix - r * 34;
            uint32_t dst = Ab + pix * 256 + ((c4 ^ ((pix & 7) << 1)) << 4);
            cp16(dst, yf4 + (((bb * HP + h0 + r) * WP + wp) * 128 + cw0 + c4));
        }
    };
    // ---- B tile stage: tap `tap`, chunk `ch` into buffer `buf` --------------
    auto issueB = [&](int tap, int ch, int buf) {
        int cw0 = ch * 16;
        uint32_t base = Bb0 + buf * B_BYTES;
#pragma unroll
        for (int k = 0; k < 16; k++) {
            int q = tid + k * 64;              // 0..1023
            int o = q >> 4, c4 = q & 15;
            uint32_t dst = base + o * 256 + ((c4 ^ ((o & 7) << 1)) << 4);
            cp16(dst, wt4 + ((tap * COUT + o) * 128 + cw0 + c4));
        }
    };

    // ---- compute one tap from resident A + B buffer -------------------------
    auto compute = [&](int tap, int buf) {
        int tk = tap / 3, tl = tap - 3 * tk;
        int prow = wm + tk;
        uint32_t apx[2][2];       // [mt][hf]: base addr incl key<<5
#pragma unroll
        for (int mt = 0; mt < 2; mt++)
#pragma unroll
            for (int hf = 0; hf < 2; hf++) {
                int p = prow * 34 + mt * 16 + g + hf * 8 + tl;
                apx[mt][hf] = (uint32_t)(p * 256 + t4 * 8 + ((p & 7) << 5));
            }
        uint32_t bbase = Bb0 + buf * B_BYTES;
#pragma unroll
        for (int ks = 0; ks < 8; ks++) {
            uint32_t xo = (uint32_t)(ks << 5);
            uint32_t a0[2], a1[2], a2[2], a3[2];
#pragma unroll
            for (int mt = 0; mt < 2; mt++) {
                lds64(Ab + (apx[mt][0] ^ xo), a0[mt], a2[mt]);
                lds64(Ab + (apx[mt][1] ^ xo), a1[mt], a3[mt]);
            }
            uint32_t b0[8], b1[8];
#pragma unroll
            for (int nf = 0; nf < 8; nf++)
                lds64(bbase + (boff[nf] ^ xo), b0[nf], b1[nf]);
#pragma unroll
            for (int mt = 0; mt < 2; mt++)
#pragma unroll
                for (int nf = 0; nf < 8; nf++)
                    mma1688(acc[mt][nf], a0[mt], a1[mt], a2[mt], a3[mt],
                            b0[nf], b1[nf]);
        }
    };

    // ---- pipeline -----------------------------------------------------------
    issueA(0);
    issueB(0, 0, 0);
    asm volatile("cp.async.commit_group;" ::: "memory");
    asm volatile("cp.async.wait_group 0;" ::: "memory");
    __syncthreads();

    int cur = 0;
    for (int ch = 0; ch < 8; ch++) {
        for (int tap = 0; tap < 9; tap++) {
            bool hn = (tap < 8);
            if (hn) {
                issueB(tap + 1, ch, cur ^ 1);
                asm volatile("cp.async.commit_group;" ::: "memory");
            }
            compute(tap, cur);
            if (hn) asm volatile("cp.async.wait_group 0;" ::: "memory");
            __syncthreads();
            if (hn) cur ^= 1;
        }
        if (ch < 7) {
            issueA(ch + 1);
            issueB(0, ch + 1, cur ^ 1);
            asm volatile("cp.async.commit_group;" ::: "memory");
            asm volatile("cp.async.wait_group 0;" ::: "memory");
            __syncthreads();
            cur ^= 1;
        }
    }

    // ---- epilogue: write out[b][o][h0+wm][wcol] -----------------------------
    int hrow = h0 + wm;
    float* obase = out + ((size_t)bb * COUT) * (H * W) + hrow * W;
#pragma unroll
    for (int mt = 0; mt < 2; mt++) {
        int wcol = mt * 16 + g;
#pragma unroll
        for (int nf = 0; nf < 8; nf++) {
            int o = nf * 8 + 2 * t4;
            obase[o * (H * W) + wcol]           = acc[mt][nf][0];
            obase[(o + 1) * (H * W) + wcol]     = acc[mt][nf][1];
            obase[o * (H * W) + wcol + 8]       = acc[mt][nf][2];
            obase[(o + 1) * (H * W) + wcol + 8] = acc[mt][nf][3];
        }
    }
}

// ---------------- launch ------------------------------------------------------
extern "C" void kernel_launch(void* const* d_in, const int* in_sizes, int n_in,
                              void* d_out, int out_size) {
    const float* x  = (const float*)d_in[0];   // [16,64,32,32]
    const float* sw = (const float*)d_in[1];   // [64,64,8,3,3]
    const float* sc = (const float*)d_in[2];   // [64,64]
    float* out = (float*)d_out;                // [16,64,32,32]

    cudaFuncSetAttribute(conv_kernel,
                         cudaFuncAttributeMaxDynamicSharedMemorySize,
                         SMEM_TOTAL);

    {
        int n = 9 * COUT * CK;
        wprep_kernel<<<(n + 255) / 256, 256>>>(sw, sc);
    }
    {
        int n = BB * HP * WP * CIN;
        basis_kernel<<<(n + 255) / 256, 256>>>(x);
    }
    conv_kernel<<<BB * (H / 2), 64, SMEM_TOTAL>>>(out);
}

// round 10
// speedup vs baseline: 1.0475x; 1.0475x over previous
#include <cuda_runtime.h>
#include <cuda_bf16.h>
#include <cstdint>

// ---------------- problem constants -----------------------------------------
static constexpr int BB = 16, CIN = 64, H = 32, W = 32, COUT = 64;
static constexpr int GS = 8;
static constexpr int HP = 34, WP = 34;
static constexpr int CK = CIN * GS;           // 512 effective channels

// ---------------- device scratch (no allocations allowed) -------------------
// A tiles: per conv-CTA, per 64-ch chunk: 136 pixels x 64 ch fp32, pre-swizzled,
// contiguous 34816 B each. [blk(256)][ch(8)] -> 71.3 MB total.
__device__ __align__(128) float g_ya[256 * 8 * 8704];
// B tiles: [ch(8)][tap(9)][o(64)][c(64)] fp32 pre-swizzled, 16384 B contiguous.
__device__ __align__(128) float g_wt2[8 * 9 * 4096];

// ---------------- helpers -----------------------------------------------------
__device__ __forceinline__ uint32_t smem_u32(const void* p) {
    uint32_t a;
    asm("{ .reg .u64 t; cvta.to.shared.u64 t, %1; cvt.u32.u64 %0, t; }"
        : "=r"(a) : "l"(p));
    return a;
}
__device__ __forceinline__ void lds64(uint32_t addr, uint32_t& r0, uint32_t& r1) {
    asm volatile("ld.shared.v2.b32 {%0,%1}, [%2];"
                 : "=r"(r0), "=r"(r1) : "r"(addr));
}
__device__ __forceinline__ void mma1688(float* c, uint32_t a0, uint32_t a1,
                                        uint32_t a2, uint32_t a3,
                                        uint32_t b0, uint32_t b1) {
    asm volatile(
        "mma.sync.aligned.m16n8k8.row.col.f32.tf32.tf32.f32 "
        "{%0,%1,%2,%3}, {%4,%5,%6,%7}, {%8,%9}, {%0,%1,%2,%3};"
        : "+f"(c[0]), "+f"(c[1]), "+f"(c[2]), "+f"(c[3])
        : "r"(a0), "r"(a1), "r"(a2), "r"(a3), "r"(b0), "r"(b1));
}
__device__ __forceinline__ float tf32r(float v) {
    uint32_t u;
    asm("cvt.rna.tf32.f32 %0, %1;" : "=r"(u) : "f"(v));
    return __uint_as_float(u);
}

#define MBAR_INIT(addr, cnt) \
    asm volatile("mbarrier.init.shared.b64 [%0], %1;" :: "r"(addr), "r"(cnt) : "memory")
#define MBAR_EXPECT_TX(addr, bytes) \
    asm volatile("mbarrier.arrive.expect_tx.shared.b64 _, [%0], %1;" \
                 :: "r"(addr), "r"(bytes) : "memory")
#define MBAR_WAIT(addr, ph) do {                                              \
    uint32_t _m = (addr); uint32_t _p = (ph); uint32_t _d;                    \
    asm volatile("{\n\t.reg .pred p;\n\t"                                     \
        "mbarrier.try_wait.parity.acquire.cta.shared::cta.b64 p, [%1], %2;\n\t" \
        "selp.b32 %0, 1, 0, p;\n\t}"                                          \
        : "=r"(_d) : "r"(_m), "r"(_p) : "memory");                            \
    if (!_d) {                                                                \
        asm volatile("{\n\t.reg .pred P1;\n\t"                                \
            "WL%=:\n\t"                                                       \
            "mbarrier.try_wait.parity.acquire.cta.shared::cta.b64 P1, [%0], %1, 0x989680;\n\t" \
            "@P1 bra.uni WD%=;\n\t"                                           \
            "bra.uni WL%=;\n\t"                                               \
            "WD%=:\n\t}" :: "r"(_m), "r"(_p) : "memory");                     \
    }                                                                         \
} while (0)

__device__ __forceinline__ void bulk_cp(uint32_t dst, const void* src,
                                        uint32_t bytes, uint32_t mbar) {
    asm volatile(
        "cp.async.bulk.shared::cta.global.mbarrier::complete_tx::bytes "
        "[%0], [%1], %2, [%3];"
        :: "r"(dst), "l"(src), "r"(bytes), "r"(mbar) : "memory");
}

// ---------------- kernel 1: weight fold, tf32, swizzled B tiles ---------------
__global__ void wprep_kernel(const float* __restrict__ sw,
                             const float* __restrict__ sc) {
    int t = blockIdx.x * blockDim.x + threadIdx.x;
    if (t >= 9 * COUT * CK) return;
    int cp = t & 511;                // permuted channel c'
    int o = (t >> 9) & 63;
    int tap = t >> 15;
    // invert permute to find source (i, g): c' = i*8 + slot, slot=((g<<1)&7)|(g>>2)
    int i = cp >> 3, slot = cp & 7;
    int g = ((slot & 1) << 2) | (slot >> 1);   // inverse of slot(g)
    float v = sw[((o * CIN + i) * GS + g) * 9 + tap] * sc[o * CIN + i];
    int ch = cp >> 6, lc = cp & 63;
    int c4 = lc >> 2;
    int swz = c4 ^ ((o & 7) << 1);
    g_wt2[(ch * 9 + tap) * 4096 + o * 64 + swz * 4 + (lc & 3)] = tf32r(v);
}

// ---------------- kernel 2: basis -> per-CTA A tiles (swizzled) ---------------
__global__ void basis_kernel(const float* __restrict__ x) {
    int idx = blockIdx.x * blockDim.x + threadIdx.x;
    if (idx >= BB * HP * WP * CIN) return;
    int i = idx & 63;
    int t = idx >> 6;
    int wp = t % WP; t /= WP;
    int hp = t % HP;
    int b = t / HP;

    float xv = 0.0f;
    int h = hp - 1, w = wp - 1;
    if ((unsigned)h < (unsigned)H && (unsigned)w < (unsigned)W)
        xv = x[((b * CIN + i) * H + h) * W + w];

    float gk[12];
#pragma unroll
    for (int j = 0; j < 12; j++) gk[j] = (float)(j - 3) * 0.4f - 1.0f;
    float b0[11];
#pragma unroll
    for (int j = 0; j < 11; j++)
        b0[j] = (xv >= gk[j] && xv < gk[j + 1]) ? 1.0f : 0.0f;
    float b1[10];
#pragma unroll
    for (int j = 0; j < 10; j++)
        b1[j] = ((xv - gk[j]) * b0[j] + (gk[j + 2] - xv) * b0[j + 1]) * 2.5f;
    float b2[9];
#pragma unroll
    for (int j = 0; j < 9; j++)
        b2[j] = ((xv - gk[j]) * b1[j] + (gk[j + 3] - xv) * b1[j + 1]) * 1.25f;
    float b3[8];
#pragma unroll
    for (int j = 0; j < 8; j++)
        b3[j] = ((xv - gk[j]) * b2[j] + (gk[j + 4] - xv) * b2[j + 1]) * (1.0f / 1.2f);

    float f[8];
#pragma unroll
    for (int g = 0; g < GS; g++) {
        int slot = ((g << 1) & 7) | (g >> 2);
        f[slot] = tf32r(b3[g]);
    }
    float4 v0 = make_float4(f[0], f[1], f[2], f[3]);
    float4 v1 = make_float4(f[4], f[5], f[6], f[7]);

    int ch = i >> 3;
    int c4a = (i & 7) * 2;
    int r0 = (hp >= 2) ? ((hp - 2) >> 1) : 0;
    int r1 = hp >> 1; if (r1 > 15) r1 = 15;
    for (int r = r0; r <= r1; r++) {
        int blk = b * 16 + r;
        int pix = (hp - 2 * r) * 34 + wp;
        int base4 = (blk * 8 + ch) * 2176 + pix * 16;   // float4 units
        int key = (pix & 7) << 1;
        ((float4*)g_ya)[base4 + (c4a ^ key)] = v0;
        ((float4*)g_ya)[base4 + ((c4a + 1) ^ key)] = v1;
    }
}

// ---------------- kernel 3: tf32 mma.sync conv, bulk-copy staged --------------
// CTA: M=64 (2 rows x 32 cols), N=64, 128 thr / 4 warps (m32 x n32 each).
// A double-buffered (34816 B) bulk tiles, B double-buffered (16384 B) bulk tiles.
static constexpr int A_BYTES = 34816;
static constexpr int B_BYTES = 16384;
static constexpr int SMEM_TOTAL = 2 * A_BYTES + 2 * B_BYTES + 1088;

__global__ __launch_bounds__(128, 2) void conv_kernel(float* __restrict__ out) {
    extern __shared__ char smem[];
    uint32_t sraw = smem_u32(smem);
    uint32_t sb = (sraw + 1023u) & ~1023u;
    uint32_t Abuf[2] = {sb, sb + A_BYTES};
    uint32_t Bbuf[2] = {sb + 2 * A_BYTES, sb + 2 * A_BYTES + B_BYTES};
    uint32_t barA[2] = {sb + 2 * A_BYTES + 2 * B_BYTES,
                        sb + 2 * A_BYTES + 2 * B_BYTES + 8};
    uint32_t barB[2] = {sb + 2 * A_BYTES + 2 * B_BYTES + 16,
                        sb + 2 * A_BYTES + 2 * B_BYTES + 24};

    int tid = threadIdx.x;
    int blk = blockIdx.x;
    int bb = blk >> 4;
    int h0 = (blk & 15) * 2;

    int lane = tid & 31;
    int wrp = tid >> 5;
    int wm = wrp & 1, wn = wrp >> 1;
    int n0w = wn * 32;
    int g = lane >> 2, t4 = lane & 3;

    if (tid == 0) {
        MBAR_INIT(barA[0], 1); MBAR_INIT(barA[1], 1);
        MBAR_INIT(barB[0], 1); MBAR_INIT(barB[1], 1);
    }
    __syncthreads();

    const char* yabase = (const char*)g_ya + (size_t)blk * 8 * A_BYTES;
    const char* wtbase = (const char*)g_wt2;

    auto issueA = [&](int ch, int buf) {
        if (tid == 0) {
            MBAR_EXPECT_TX(barA[buf], A_BYTES);
            bulk_cp(Abuf[buf], yabase + (size_t)ch * A_BYTES, A_BYTES, barA[buf]);
        }
    };
    auto issueB = [&](int ch, int tap, int buf) {
        if (tid == 0) {
            MBAR_EXPECT_TX(barB[buf], B_BYTES);
            bulk_cp(Bbuf[buf], wtbase + (size_t)(ch * 9 + tap) * B_BYTES,
                    B_BYTES, barB[buf]);
        }
    };

    uint32_t boff[4];
#pragma unroll
    for (int nf = 0; nf < 4; nf++)
        boff[nf] = (uint32_t)((n0w + nf * 8 + g) * 256 + t4 * 8 + (g << 5));

    float acc[2][4][4];
#pragma unroll
    for (int a = 0; a < 2; a++)
#pragma unroll
        for (int b = 0; b < 4; b++)
#pragma unroll
            for (int i = 0; i < 4; i++) acc[a][b][i] = 0.0f;

    auto compute = [&](int tap, uint32_t Ab, uint32_t Bb) {
        int tk = tap / 3, tl = tap - 3 * tk;
        int prow = wm + tk;
        uint32_t apx[2][2];
#pragma unroll
        for (int mt = 0; mt < 2; mt++)
#pragma unroll
            for (int hf = 0; hf < 2; hf++) {
                int p = prow * 34 + mt * 16 + g + hf * 8 + tl;
                apx[mt][hf] = (uint32_t)(p * 256 + t4 * 8 + ((p & 7) << 5));
            }
#pragma unroll
        for (int ks = 0; ks < 8; ks++) {
            uint32_t xo = (uint32_t)(ks << 5);
            uint32_t a0[2], a1[2], a2[2], a3[2];
#pragma unroll
            for (int mt = 0; mt < 2; mt++) {
                lds64(Ab + (apx[mt][0] ^ xo), a0[mt], a2[mt]);
                lds64(Ab + (apx[mt][1] ^ xo), a1[mt], a3[mt]);
            }
            uint32_t b0[4], b1[4];
#pragma unroll
            for (int nf = 0; nf < 4; nf++)
                lds64(Bb + (boff[nf] ^ xo), b0[nf], b1[nf]);
#pragma unroll
            for (int mt = 0; mt < 2; mt++)
#pragma unroll
                for (int nf = 0; nf < 4; nf++)
                    mma1688(acc[mt][nf], a0[mt], a1[mt], a2[mt], a3[mt],
                            b0[nf], b1[nf]);
        }
    };

    // ---- pipeline -----------------------------------------------------------
    issueA(0, 0);
    issueB(0, 0, 0);

    int curA = 0, curB = 0;
    int pa[2] = {0, 0}, pb[2] = {0, 0};
    for (int ch = 0; ch < 8; ch++) {
        __syncthreads();                       // WAR: A[curA^1] free
        if (ch < 7) issueA(ch + 1, curA ^ 1);
        MBAR_WAIT(barA[curA], pa[curA]); pa[curA] ^= 1;
        for (int tap = 0; tap < 9; tap++) {
            __syncthreads();                   // WAR: B[curB^1] free
            int tnext = ch * 9 + tap + 1;
            if (tnext < 72) issueB(tnext / 9, tnext % 9, curB ^ 1);
            MBAR_WAIT(barB[curB], pb[curB]); pb[curB] ^= 1;
            compute(tap, Abuf[curA], Bbuf[curB]);
            curB ^= 1;
        }
        curA ^= 1;
    }

    // ---- epilogue -----------------------------------------------------------
    int hrow = h0 + wm;
    float* obase = out + ((size_t)bb * COUT) * (H * W) + hrow * W;
#pragma unroll
    for (int mt = 0; mt < 2; mt++) {
        int wcol = mt * 16 + g;
#pragma unroll
        for (int nf = 0; nf < 4; nf++) {
            int o = n0w + nf * 8 + 2 * t4;
            obase[o * (H * W) + wcol]           = acc[mt][nf][0];
            obase[(o + 1) * (H * W) + wcol]     = acc[mt][nf][1];
            obase[o * (H * W) + wcol + 8]       = acc[mt][nf][2];
            obase[(o + 1) * (H * W) + wcol + 8] = acc[mt][nf][3];
        }
    }
}

// ---------------- launch ------------------------------------------------------
extern "C" void kernel_launch(void* const* d_in, const int* in_sizes, int n_in,
                              void* d_out, int out_size) {
    const float* x  = (const float*)d_in[0];   // [16,64,32,32]
    const float* sw = (const float*)d_in[1];   // [64,64,8,3,3]
    const float* sc = (const float*)d_in[2];   // [64,64]
    float* out = (float*)d_out;                // [16,64,32,32]

    cudaFuncSetAttribute(conv_kernel,
                         cudaFuncAttributeMaxDynamicSharedMemorySize,
                         SMEM_TOTAL);

    {
        int n = 9 * COUT * CK;
        wprep_kernel<<<(n + 255) / 256, 256>>>(sw, sc);
    }
    {
        int n = BB * HP * WP * CIN;
        basis_kernel<<<(n + 255) / 256, 256>>>(x);
    }
    conv_kernel<<<BB * (H / 2), 128, SMEM_TOTAL>>>(out);
}